// round 5
// baseline (speedup 1.0000x reference)
#include <cuda_runtime.h>
#include <mma.h>
#include <math.h>
#include <cstdint>

using namespace nvcuda;

#define D 128
#define MAX_N 100096
#define CAP 96
#define BROWS 128

// Scratch (allocation-free rule: __device__ globals).
__device__ float g_h[(size_t)MAX_N * D];          // SpMM accumulator
__device__ int   g_cnt[MAX_N];                    // per-node edge count
__device__ int2  g_edge[(size_t)MAX_N * CAP];     // edge buckets (src, w-bits)

// ---------------------------------------------------------------------------
__global__ void zero_kernel(int n) {
    int i = blockIdx.x * blockDim.x + threadIdx.x;
    if (i < n) g_cnt[i] = 0;
}

// ---------------------------------------------------------------------------
__global__ void scatter_kernel(const float* __restrict__ H,
                               const int*   __restrict__ src,
                               const int*   __restrict__ dst,
                               const float* __restrict__ ew,
                               int E) {
    int i = blockIdx.x * blockDim.x + threadIdx.x;
    if (i >= E) return;
    int d = dst[i];
    int pos = atomicAdd(&g_cnt[d], 1);
    int s = src[i];
    float w = ew[i];
    if (pos < CAP) {
        g_edge[(size_t)d * CAP + pos] = make_int2(s, __float_as_int(w));
    } else {
        // Statistically unreachable overflow; gather merges via cnt>CAP path.
        const float4* hp = (const float4*)(H + (size_t)s * D);
        float* o = g_h + (size_t)d * D;
        #pragma unroll 4
        for (int c = 0; c < D / 4; c++) {
            float4 v = __ldg(hp + c);
            asm volatile("red.global.add.v4.f32 [%0], {%1, %2, %3, %4};"
                         :: "l"(o + c * 4),
                            "f"(v.x * w), "f"(v.y * w), "f"(v.z * w), "f"(v.w * w)
                         : "memory");
        }
    }
}

// ---------------------------------------------------------------------------
__global__ __launch_bounds__(256)
void gather_kernel(const float* __restrict__ H, int N) {
    int warp = (int)((blockIdx.x * (unsigned)blockDim.x + threadIdx.x) >> 5);
    int lane = threadIdx.x & 31;
    if (warp >= N) return;

    int cnt = g_cnt[warp];
    int deg = cnt < CAP ? cnt : CAP;
    const int2* lst = g_edge + (size_t)warp * CAP;

    float4 acc = make_float4(0.f, 0.f, 0.f, 0.f);

    int e = 0;
    for (; e + 4 <= deg; e += 4) {
        int4 a = __ldg((const int4*)(lst + e));
        int4 b = __ldg((const int4*)(lst + e) + 1);
        float w0 = __int_as_float(a.y), w1 = __int_as_float(a.w);
        float w2 = __int_as_float(b.y), w3 = __int_as_float(b.w);
        float4 v0 = __ldg((const float4*)(H + (size_t)a.x * D) + lane);
        float4 v1 = __ldg((const float4*)(H + (size_t)a.z * D) + lane);
        float4 v2 = __ldg((const float4*)(H + (size_t)b.x * D) + lane);
        float4 v3 = __ldg((const float4*)(H + (size_t)b.z * D) + lane);
        acc.x += w0 * v0.x; acc.y += w0 * v0.y; acc.z += w0 * v0.z; acc.w += w0 * v0.w;
        acc.x += w1 * v1.x; acc.y += w1 * v1.y; acc.z += w1 * v1.z; acc.w += w1 * v1.w;
        acc.x += w2 * v2.x; acc.y += w2 * v2.y; acc.z += w2 * v2.z; acc.w += w2 * v2.w;
        acc.x += w3 * v3.x; acc.y += w3 * v3.y; acc.z += w3 * v3.z; acc.w += w3 * v3.w;
    }
    for (; e < deg; e++) {
        int2 p = __ldg(lst + e);
        float w = __int_as_float(p.y);
        float4 v = __ldg((const float4*)(H + (size_t)p.x * D) + lane);
        acc.x += w * v.x; acc.y += w * v.y; acc.z += w * v.z; acc.w += w * v.w;
    }

    float4* o = (float4*)(g_h + (size_t)warp * D) + lane;
    if (cnt > CAP) {
        float4 old = *o;
        acc.x += old.x; acc.y += old.y; acc.z += old.z; acc.w += old.w;
    }
    *o = acc;
}

// ---------------------------------------------------------------------------
// Kernel 4: fused BN -> Dense (TF32 tensor cores, 3-term split) -> exact GELU.
// Tile 128x128 per CTA, 8 warps (warp = 32m x 64n), K in 4 panels of 32.
// ---------------------------------------------------------------------------
__device__ __forceinline__ float gelu_exact(float x) {
    return 0.5f * x * (1.0f + erff(x * 0.70710678118654752f));
}

__device__ __forceinline__ float tf32_rna(float x) {
    unsigned int r;
    asm("cvt.rna.tf32.f32 %0, %1;" : "=r"(r) : "f"(x));
    return __uint_as_float(r);
}

#define LDA 40      // 32 + 8 pad (A panels: 128 rows x 32 k)
#define LDW 136     // 128 + 8 pad (W panels: 32 k x 128 c; also epilogue tile)
#define A_HI 0
#define A_LO (A_HI + BROWS * LDA)          // 5120
#define W_HI (A_LO + BROWS * LDA)          // 10240
#define W_LO (W_HI + 32 * LDW)             // 14592
#define SMEM_F (W_LO + 32 * LDW)           // 18944 floats = 75776 B

__global__ __launch_bounds__(256)
void gemm_kernel(const float* __restrict__ W,
                 const float* __restrict__ bias,
                 const float* __restrict__ gamma,
                 const float* __restrict__ beta,
                 const float* __restrict__ mean,
                 const float* __restrict__ var,
                 float* __restrict__ out,
                 int N) {
    extern __shared__ float sm[];
    __shared__ float sScale[D], sShift[D];

    int tid = threadIdx.x;
    if (tid < D) {
        float sc = gamma[tid] * rsqrtf(var[tid] + 1e-3f);
        sScale[tid] = sc;
        sShift[tid] = beta[tid] - mean[tid] * sc;
    }

    int row0 = blockIdx.x * BROWS;
    int wid  = tid >> 5;
    int m0   = (wid >> 1) * 32;     // warp row offset within tile
    int n0   = (wid & 1) * 64;      // warp col offset within tile

    wmma::fragment<wmma::accumulator, 16, 16, 8, float> acc[2][4];
    #pragma unroll
    for (int mf = 0; mf < 2; mf++)
        #pragma unroll
        for (int nf = 0; nf < 4; nf++) wmma::fill_fragment(acc[mf][nf], 0.0f);

    __syncthreads();   // sScale/sShift ready

    for (int p = 0; p < 4; p++) {
        int k0 = p * 32;

        // Stage A panel (BN applied, tf32 hi/lo split): 128 rows x 32 k.
        #pragma unroll
        for (int t = 0; t < 4; t++) {
            int i  = tid + t * 256;          // 0..1023
            int r  = i >> 3;                 // row 0..127
            int c4 = i & 7;                  // float4 within the 32-k panel
            int gr = row0 + r;
            float4 v = make_float4(0.f, 0.f, 0.f, 0.f);
            if (gr < N) v = __ldg((const float4*)(g_h + (size_t)gr * D) + (k0 >> 2) + c4);
            int c = k0 + c4 * 4;
            float x0 = v.x * sScale[c + 0] + sShift[c + 0];
            float x1 = v.y * sScale[c + 1] + sShift[c + 1];
            float x2 = v.z * sScale[c + 2] + sShift[c + 2];
            float x3 = v.w * sScale[c + 3] + sShift[c + 3];
            float h0 = tf32_rna(x0), h1 = tf32_rna(x1);
            float h2 = tf32_rna(x2), h3 = tf32_rna(x3);
            int o = r * LDA + c4 * 4;
            sm[A_HI + o + 0] = h0; sm[A_HI + o + 1] = h1;
            sm[A_HI + o + 2] = h2; sm[A_HI + o + 3] = h3;
            sm[A_LO + o + 0] = x0 - h0; sm[A_LO + o + 1] = x1 - h1;
            sm[A_LO + o + 2] = x2 - h2; sm[A_LO + o + 3] = x3 - h3;
        }

        // Stage W panel (tf32 hi/lo split): 32 k x 128 c.
        #pragma unroll
        for (int t = 0; t < 4; t++) {
            int i  = tid + t * 256;          // 0..1023
            int k  = i >> 5;                 // 0..31
            int c4 = i & 31;                 // 32 float4 per 128-col row
            float4 v = __ldg((const float4*)(W + (size_t)(k0 + k) * D) + c4);
            float h0 = tf32_rna(v.x), h1 = tf32_rna(v.y);
            float h2 = tf32_rna(v.z), h3 = tf32_rna(v.w);
            int o = k * LDW + c4 * 4;
            sm[W_HI + o + 0] = h0; sm[W_HI + o + 1] = h1;
            sm[W_HI + o + 2] = h2; sm[W_HI + o + 3] = h3;
            sm[W_LO + o + 0] = v.x - h0; sm[W_LO + o + 1] = v.y - h1;
            sm[W_LO + o + 2] = v.z - h2; sm[W_LO + o + 3] = v.w - h3;
        }
        __syncthreads();

        #pragma unroll
        for (int kk = 0; kk < 4; kk++) {     // 4 k-steps of 8
            wmma::fragment<wmma::matrix_a, 16, 16, 8, wmma::precision::tf32, wmma::row_major> aHi[2], aLo[2];
            #pragma unroll
            for (int mf = 0; mf < 2; mf++) {
                const float* ap = sm + A_HI + (m0 + mf * 16) * LDA + kk * 8;
                const float* al = sm + A_LO + (m0 + mf * 16) * LDA + kk * 8;
                wmma::load_matrix_sync(aHi[mf], ap, LDA);
                wmma::load_matrix_sync(aLo[mf], al, LDA);
            }
            #pragma unroll
            for (int nf = 0; nf < 4; nf++) {
                wmma::fragment<wmma::matrix_b, 16, 16, 8, wmma::precision::tf32, wmma::row_major> bHi, bLo;
                const float* bp = sm + W_HI + kk * 8 * LDW + n0 + nf * 16;
                const float* bl = sm + W_LO + kk * 8 * LDW + n0 + nf * 16;
                wmma::load_matrix_sync(bHi, bp, LDW);
                wmma::load_matrix_sync(bLo, bl, LDW);
                #pragma unroll
                for (int mf = 0; mf < 2; mf++) {
                    wmma::mma_sync(acc[mf][nf], aHi[mf], bHi, acc[mf][nf]);
                    wmma::mma_sync(acc[mf][nf], aHi[mf], bLo, acc[mf][nf]);
                    wmma::mma_sync(acc[mf][nf], aLo[mf], bHi, acc[mf][nf]);
                }
            }
        }
        __syncthreads();
    }

    // Epilogue: dump accs to smem tile (128 x LDW), bias + exact GELU, store.
    #pragma unroll
    for (int mf = 0; mf < 2; mf++)
        #pragma unroll
        for (int nf = 0; nf < 4; nf++)
            wmma::store_matrix_sync(sm + (m0 + mf * 16) * LDW + n0 + nf * 16,
                                    acc[mf][nf], LDW, wmma::mem_row_major);
    __syncthreads();

    #pragma unroll
    for (int t = 0; t < 16; t++) {
        int i  = tid + t * 256;              // 0..4095  (128 rows x 32 float4)
        int r  = i >> 5;
        int c4 = i & 31;
        int gr = row0 + r;
        if (gr >= N) continue;
        int c = c4 * 4;
        const float* s = sm + r * LDW + c;
        float4 o;
        o.x = gelu_exact(s[0] + bias[c + 0]);
        o.y = gelu_exact(s[1] + bias[c + 1]);
        o.z = gelu_exact(s[2] + bias[c + 2]);
        o.w = gelu_exact(s[3] + bias[c + 3]);
        ((float4*)(out + (size_t)gr * D))[c4] = o;
    }
}

// ---------------------------------------------------------------------------
extern "C" void kernel_launch(void* const* d_in, const int* in_sizes, int n_in,
                              void* d_out, int out_size) {
    const float* H     = (const float*)d_in[0];
    const int*   src   = (const int*)  d_in[1];
    const int*   dst   = (const int*)  d_in[2];
    const float* ew    = (const float*)d_in[3];
    const float* gamma = (const float*)d_in[4];
    const float* beta  = (const float*)d_in[5];
    const float* mean  = (const float*)d_in[6];
    const float* var   = (const float*)d_in[7];
    const float* W     = (const float*)d_in[8];
    const float* bias  = (const float*)d_in[9];

    int N = in_sizes[0] / D;
    int E = in_sizes[1];

    zero_kernel<<<(N + 255) / 256, 256>>>(N);

    scatter_kernel<<<(E + 255) / 256, 256>>>(H, src, dst, ew, E);

    gather_kernel<<<(N * 32 + 255) / 256, 256>>>(H, N);

    int smem_bytes = SMEM_F * sizeof(float);   // ~74 KB
    cudaFuncSetAttribute(gemm_kernel,
                         cudaFuncAttributeMaxDynamicSharedMemorySize, smem_bytes);
    gemm_kernel<<<(N + BROWS - 1) / BROWS, 256, smem_bytes>>>(
        W, bias, gamma, beta, mean, var, (float*)d_out, N);
}